// round 1
// baseline (speedup 1.0000x reference)
#include <cuda_runtime.h>
#include <math.h>

#define NN   30000
#define EE   300000
#define RR   3
#define IND  256
#define HID  32
#define OUTD 64
#define HEADS 4
#define C1 (HEADS*HID)    // 128
#define C2 (HEADS*OUTD)   // 256
#define NEG_SLOPE 0.2f

// -------------------- device scratch (static; no runtime alloc) --------------------
__device__ float g_z1[(size_t)RR*NN*C1];       // 46 MB
__device__ float g_z2[(size_t)RR*NN*C2];       // 92 MB
__device__ float g_el[(size_t)RR*NN*HEADS];
__device__ float g_er[(size_t)RR*NN*HEADS];
__device__ float g_m [(size_t)RR*NN*HEADS];
__device__ float g_den[(size_t)RR*NN*HEADS];
__device__ float g_e [(size_t)RR*EE*HEADS];    // 14.4 MB (reused both layers)
__device__ float g_h [(size_t)NN*C1];          // conv1 output accumulator
__device__ float g_h2[(size_t)NN*C2];          // conv2 output accumulator

// -------------------- helpers --------------------
__device__ __forceinline__ void atomicMaxF(float* addr, float val) {
    int old = __float_as_int(*addr);
    while (__int_as_float(old) < val) {
        int assumed = old;
        old = atomicCAS((int*)addr, assumed, __float_as_int(val));
        if (old == assumed) break;
    }
}

// -------------------- init --------------------
// which==0: zero g_h (layer1);  which==1: zero g_h2 (layer2). Always resets m/den.
__global__ void init_k(int which) {
    long i = (long)blockIdx.x * blockDim.x + threadIdx.x;
    if (i < (long)RR*NN*HEADS) { g_m[i] = -INFINITY; g_den[i] = 0.f; }
    if (which == 0) { if (i < (long)NN*C1) g_h[i] = 0.f; }
    else            { if (i < (long)NN*C2) g_h2[i] = 0.f; }
}

// -------------------- tiled fp32 GEMM: C[r] = A @ B[r] --------------------
// A: [M,K] row-major (shared across relations), B: [R,K,Ncols], C: [R,M,Ncols]
template<int BM, int BN, int BK>
__global__ void gemm_rel(const float* __restrict__ A, const float* __restrict__ B,
                         float* __restrict__ C, int M, int Ncols, int K) {
    int r = blockIdx.z;
    const float* Bp = B + (size_t)r * K * Ncols;
    float*       Cp = C + (size_t)r * M * Ncols;

    __shared__ float As[BK][BM+1];
    __shared__ float Bs[BK][BN+1];

    int tid  = threadIdx.x;          // 256 threads
    int tcol = tid & 15;
    int trow = tid >> 4;
    int rowBase = blockIdx.x * BM;
    int colBase = blockIdx.y * BN;

    float acc[4][4] = {};

    for (int k0 = 0; k0 < K; k0 += BK) {
        #pragma unroll
        for (int i = 0; i < (BM*BK)/256; i++) {
            int e = i*256 + tid;
            int m = e >> 4, kk = e & 15;        // BK=16
            int gm = rowBase + m;
            As[kk][m] = (gm < M) ? A[(size_t)gm*K + k0 + kk] : 0.f;
        }
        #pragma unroll
        for (int i = 0; i < (BN*BK)/256; i++) {
            int e = i*256 + tid;
            int kk = e >> 6, n = e & 63;        // BN=64
            Bs[kk][n] = Bp[(size_t)(k0+kk)*Ncols + colBase + n];
        }
        __syncthreads();
        #pragma unroll
        for (int kk = 0; kk < BK; kk++) {
            float am[4], bn[4];
            #pragma unroll
            for (int i = 0; i < 4; i++) am[i] = As[kk][trow*4 + i];
            #pragma unroll
            for (int j = 0; j < 4; j++) bn[j] = Bs[kk][tcol*4 + j];
            #pragma unroll
            for (int i = 0; i < 4; i++)
                #pragma unroll
                for (int j = 0; j < 4; j++)
                    acc[i][j] += am[i] * bn[j];
        }
        __syncthreads();
    }
    #pragma unroll
    for (int i = 0; i < 4; i++) {
        int gm = rowBase + trow*4 + i;
        if (gm < M) {
            #pragma unroll
            for (int j = 0; j < 4; j++)
                Cp[(size_t)gm*Ncols + colBase + tcol*4 + j] = acc[i][j];
        }
    }
}

// -------------------- attention dot products --------------------
// One 128-thread block per (r,n); warp w handles head w; lane strides dim D.
__global__ void attn_dots(const float* __restrict__ z, const float* __restrict__ al,
                          const float* __restrict__ ar, int D) {
    long bid = blockIdx.x;                   // r*NN + n
    int r = (int)(bid / NN), n = (int)(bid % NN);
    int t = threadIdx.x, h = t >> 5, lane = t & 31;
    int Ccols = HEADS * D;
    const float* zrow = z  + ((size_t)r*NN + n) * Ccols + h * D;
    const float* alp  = al + ((size_t)r*HEADS + h) * D;
    const float* arp  = ar + ((size_t)r*HEADS + h) * D;
    float vl = 0.f, vr = 0.f;
    for (int d = lane; d < D; d += 32) {
        float zv = zrow[d];
        vl += zv * alp[d];
        vr += zv * arp[d];
    }
    #pragma unroll
    for (int off = 16; off; off >>= 1) {
        vl += __shfl_down_sync(0xffffffffu, vl, off);
        vr += __shfl_down_sync(0xffffffffu, vr, off);
    }
    if (lane == 0) {
        g_el[((size_t)r*NN + n)*HEADS + h] = vl;
        g_er[((size_t)r*NN + n)*HEADS + h] = vr;
    }
}

// -------------------- edge pass A: leaky-relu scores + segment max --------------------
__global__ void edge_max(const int* __restrict__ src, const int* __restrict__ dst) {
    long i = (long)blockIdx.x * blockDim.x + threadIdx.x;
    if (i >= (long)RR*EE*HEADS) return;
    int h = (int)(i % HEADS);
    long t = i / HEADS;
    int e = (int)(t % EE), r = (int)(t / EE);
    int s = src[(size_t)r*EE + e], d = dst[(size_t)r*EE + e];
    float v = g_el[((size_t)r*NN + s)*HEADS + h] + g_er[((size_t)r*NN + d)*HEADS + h];
    v = v > 0.f ? v : NEG_SLOPE * v;
    g_e[i] = v;
    atomicMaxF(&g_m[((size_t)r*NN + d)*HEADS + h], v);
}

// -------------------- edge pass B: exp + segment sum --------------------
__global__ void edge_exp(const int* __restrict__ dst) {
    long i = (long)blockIdx.x * blockDim.x + threadIdx.x;
    if (i >= (long)RR*EE*HEADS) return;
    int h = (int)(i % HEADS);
    long t = i / HEADS;
    int e = (int)(t % EE), r = (int)(t / EE);
    int d = dst[(size_t)r*EE + e];
    float w = expf(g_e[i] - g_m[((size_t)r*NN + d)*HEADS + h]);
    g_e[i] = w;
    atomicAdd(&g_den[((size_t)r*NN + d)*HEADS + h], w);
}

// -------------------- edge pass C: normalize + scatter --------------------
// One block per (r,e); HEADS*D threads, thread c covers channel c (h = c/D).
__global__ void edge_scatter(const int* __restrict__ src, const int* __restrict__ dst,
                             const float* __restrict__ z, float* __restrict__ out, int D) {
    long b = blockIdx.x;                     // r*EE + e
    int e = (int)(b % EE), r = (int)(b / EE);
    int c = threadIdx.x, h = c / D;
    int Ccols = HEADS * D;
    int s = src[(size_t)r*EE + e], d = dst[(size_t)r*EE + e];
    float w  = g_e[((size_t)r*EE + e)*HEADS + h];
    float dn = g_den[((size_t)r*NN + d)*HEADS + h];
    float val = (w / dn) * z[((size_t)r*NN + s)*Ccols + c];
    atomicAdd(&out[(size_t)d*Ccols + c], val);
}

// -------------------- layer-1 epilogue: +sum_r(b1) then ReLU --------------------
__global__ void finish1(const float* __restrict__ b1) {
    long i = (long)blockIdx.x * blockDim.x + threadIdx.x;
    if (i >= (long)NN*C1) return;
    int c = (int)(i % C1);
    float v = g_h[i] + b1[c] + b1[C1 + c] + b1[2*C1 + c];
    g_h[i] = v > 0.f ? v : 0.f;
}

// -------------------- final: +sum_r(b2), mean over heads --------------------
__global__ void final_k(const float* __restrict__ b2, float* __restrict__ out) {
    long i = (long)blockIdx.x * blockDim.x + threadIdx.x;
    if (i >= (long)NN*OUTD) return;
    int n = (int)(i / OUTD), o = (int)(i % OUTD);
    float acc = 0.f;
    #pragma unroll
    for (int hh = 0; hh < HEADS; hh++) {
        int c = hh*OUTD + o;
        acc += g_h2[(size_t)n*C2 + c] + b2[c] + b2[C2 + c] + b2[2*C2 + c];
    }
    out[i] = acc * 0.25f;
}

// -------------------- launch --------------------
extern "C" void kernel_launch(void* const* d_in, const int* in_sizes, int n_in,
                              void* d_out, int out_size) {
    const float* x   = (const float*)d_in[0];
    const int*   src = (const int*)  d_in[1];
    const int*   dst = (const int*)  d_in[2];
    const float* W1  = (const float*)d_in[3];
    const float* al1 = (const float*)d_in[4];
    const float* ar1 = (const float*)d_in[5];
    const float* b1  = (const float*)d_in[6];
    const float* W2  = (const float*)d_in[7];
    const float* al2 = (const float*)d_in[8];
    const float* ar2 = (const float*)d_in[9];
    const float* b2  = (const float*)d_in[10];
    float* out = (float*)d_out;

    float *z1p, *z2p, *hp, *h2p;
    cudaGetSymbolAddress((void**)&z1p, g_z1);
    cudaGetSymbolAddress((void**)&z2p, g_z2);
    cudaGetSymbolAddress((void**)&hp,  g_h);
    cudaGetSymbolAddress((void**)&h2p, g_h2);

    const int edgeThreads = 256;
    const long edgeItems = (long)RR*EE*HEADS;                 // 3.6M
    const int edgeBlocks = (int)((edgeItems + edgeThreads - 1) / edgeThreads);

    // ---------- layer 1 ----------
    init_k<<<30000, 256>>>(0);
    gemm_rel<64,64,16><<<dim3((NN+63)/64, C1/64, RR), 256>>>(x, W1, z1p, NN, C1, IND);
    attn_dots<<<RR*NN, 128>>>(z1p, al1, ar1, HID);
    edge_max<<<edgeBlocks, edgeThreads>>>(src, dst);
    edge_exp<<<edgeBlocks, edgeThreads>>>(dst);
    edge_scatter<<<RR*EE, C1>>>(src, dst, z1p, hp, HID);
    finish1<<<(NN*C1 + 255)/256, 256>>>(b1);

    // ---------- layer 2 ----------
    init_k<<<30000, 256>>>(1);
    gemm_rel<64,64,16><<<dim3((NN+63)/64, C2/64, RR), 256>>>(hp, W2, z2p, NN, C2, C1);
    attn_dots<<<RR*NN, 128>>>(z2p, al2, ar2, OUTD);
    edge_max<<<edgeBlocks, edgeThreads>>>(src, dst);
    edge_exp<<<edgeBlocks, edgeThreads>>>(dst);
    edge_scatter<<<RR*EE, C2>>>(src, dst, z2p, h2p, OUTD);
    final_k<<<(NN*OUTD + 255)/256, 256>>>(b2, out);
}

// round 2
// speedup vs baseline: 1.5523x; 1.5523x over previous
#include <cuda_runtime.h>
#include <math.h>

#define NN   30000
#define EE   300000
#define RR   3
#define IND  256
#define HID  32
#define OUTD 64
#define HEADS 4
#define C1 (HEADS*HID)    // 128
#define C2 (HEADS*OUTD)   // 256
#define NEG_SLOPE 0.2f

// -------------------- device scratch (static; no runtime alloc) --------------------
__device__ float g_z1[(size_t)RR*NN*C1];       // 46 MB
__device__ float g_z2[(size_t)RR*NN*C2];       // 92 MB
__device__ float g_el[(size_t)RR*NN*HEADS];
__device__ float g_er[(size_t)RR*NN*HEADS];
__device__ float g_h [(size_t)NN*C1];          // conv1 output (post-ReLU)
// CSR by destination (shared by both layers)
__device__ int g_cnt [(size_t)RR*NN];
__device__ int g_ptr [(size_t)RR*NN + 1];
__device__ int g_cur [(size_t)RR*NN];
__device__ int g_list[(size_t)RR*EE];          // stores SRC node ids grouped by (r,dst)

// ==================== CSR build ====================
__global__ void zero_cnt_k() {
    int i = blockIdx.x * blockDim.x + threadIdx.x;
    if (i < RR*NN) g_cnt[i] = 0;
}

__global__ void hist_k(const int* __restrict__ dst) {
    int i = blockIdx.x * blockDim.x + threadIdx.x;
    if (i >= RR*EE) return;
    int r = i / EE;
    atomicAdd(&g_cnt[r*NN + dst[i]], 1);
}

// single-block exclusive scan over RR*NN counters
__global__ void scan_k() {
    __shared__ int s[1024];
    __shared__ int carry;
    int tid = threadIdx.x;
    if (tid == 0) carry = 0;
    __syncthreads();
    const int TOT = RR*NN;
    for (int base = 0; base < TOT; base += 1024) {
        int i = base + tid;
        int v = (i < TOT) ? g_cnt[i] : 0;
        s[tid] = v;
        __syncthreads();
        #pragma unroll
        for (int off = 1; off < 1024; off <<= 1) {
            int t = (tid >= off) ? s[tid - off] : 0;
            __syncthreads();
            s[tid] += t;
            __syncthreads();
        }
        if (i < TOT) {
            g_ptr[i] = carry + s[tid] - v;   // exclusive
            g_cur[i] = carry + s[tid] - v;
        }
        __syncthreads();
        if (tid == 1023) carry += s[1023];
        __syncthreads();
    }
    if (tid == 0) g_ptr[TOT] = carry;
}

__global__ void fill_k(const int* __restrict__ src, const int* __restrict__ dst) {
    int i = blockIdx.x * blockDim.x + threadIdx.x;
    if (i >= RR*EE) return;
    int r = i / EE;
    int pos = atomicAdd(&g_cur[r*NN + dst[i]], 1);
    g_list[pos] = src[i];
}

// ==================== SGEMM: C[r] = A @ B[r]  (128x128x8, 8x8 microtile) ====================
__global__ __launch_bounds__(256, 2)
void sgemm_rel(const float* __restrict__ A, const float* __restrict__ B,
               float* __restrict__ C, int M, int Ncols, int K) {
    const int BM = 128, BN = 128, BK = 8;
    int r = blockIdx.z;
    const float* Bp = B + (size_t)r * K * Ncols;
    float*       Cp = C + (size_t)r * M * Ncols;

    __shared__ float As[BK][BM];   // transposed: As[k][m]
    __shared__ float Bs[BK][BN];

    int tid = threadIdx.x;
    int tx = tid & 15, ty = tid >> 4;
    int row0 = blockIdx.x * BM, col0 = blockIdx.y * BN;

    // A-load mapping: 256 threads x 1 float4 = 128 rows x 8 k
    int aRow = tid >> 1;
    int aK4  = (tid & 1) * 4;
    // B-load mapping: 8 k-rows x 32 float4
    int bK  = tid >> 5;
    int bN4 = (tid & 31) * 4;

    float acc[8][8] = {};

    for (int k0 = 0; k0 < K; k0 += BK) {
        int gm = row0 + aRow;
        float4 av = make_float4(0.f, 0.f, 0.f, 0.f);
        if (gm < M)
            av = *(const float4*)&A[(size_t)gm*K + k0 + aK4];
        As[aK4+0][aRow] = av.x;
        As[aK4+1][aRow] = av.y;
        As[aK4+2][aRow] = av.z;
        As[aK4+3][aRow] = av.w;

        float4 bvv = *(const float4*)&Bp[(size_t)(k0+bK)*Ncols + col0 + bN4];
        *(float4*)&Bs[bK][bN4] = bvv;
        __syncthreads();

        #pragma unroll
        for (int kk = 0; kk < BK; kk++) {
            float a_[8], b_[8];
            *(float4*)&a_[0] = *(const float4*)&As[kk][ty*8];
            *(float4*)&a_[4] = *(const float4*)&As[kk][ty*8+4];
            *(float4*)&b_[0] = *(const float4*)&Bs[kk][tx*8];
            *(float4*)&b_[4] = *(const float4*)&Bs[kk][tx*8+4];
            #pragma unroll
            for (int i = 0; i < 8; i++)
                #pragma unroll
                for (int j = 0; j < 8; j++)
                    acc[i][j] += a_[i] * b_[j];
        }
        __syncthreads();
    }

    #pragma unroll
    for (int i = 0; i < 8; i++) {
        int gm = row0 + ty*8 + i;
        if (gm < M) {
            float* cp = &Cp[(size_t)gm*Ncols + col0 + tx*8];
            *(float4*)&cp[0] = *(float4*)&acc[i][0];
            *(float4*)&cp[4] = *(float4*)&acc[i][4];
        }
    }
}

// ==================== attention dot products ====================
__global__ void attn_dots(const float* __restrict__ z, const float* __restrict__ al,
                          const float* __restrict__ ar, int D) {
    long bid = blockIdx.x;                   // r*NN + n
    int r = (int)(bid / NN);
    int t = threadIdx.x, h = t >> 5, lane = t & 31;
    int Ccols = HEADS * D;
    const float* zrow = z  + (size_t)bid * Ccols + h * D;
    const float* alp  = al + ((size_t)r*HEADS + h) * D;
    const float* arp  = ar + ((size_t)r*HEADS + h) * D;
    float vl = 0.f, vr = 0.f;
    for (int d = lane; d < D; d += 32) {
        float zv = zrow[d];
        vl += zv * alp[d];
        vr += zv * arp[d];
    }
    #pragma unroll
    for (int off = 16; off; off >>= 1) {
        vl += __shfl_down_sync(0xffffffffu, vl, off);
        vr += __shfl_down_sync(0xffffffffu, vr, off);
    }
    if (lane == 0) {
        g_el[(size_t)bid*HEADS + h] = vl;
        g_er[(size_t)bid*HEADS + h] = vr;
    }
}

// ==================== fused GAT aggregation, layer 1 ====================
// one block (128 thr) per dst node; thread c owns channel c; h = c/32
__global__ __launch_bounds__(C1)
void gat_agg1(const float* __restrict__ z, const float* __restrict__ b1) {
    int n = blockIdx.x;
    int c = threadIdx.x, h = c >> 5;
    float acc = 0.f;
    #pragma unroll
    for (int r = 0; r < RR; r++) {
        int p0 = g_ptr[r*NN + n], p1 = g_ptr[r*NN + n + 1];
        if (p0 == p1) continue;
        float erv = g_er[((size_t)r*NN + n)*HEADS + h];
        const float* elp = g_el + (size_t)r*NN*HEADS;
        float m = -INFINITY;
        for (int j = p0; j < p1; j++) {
            int s = g_list[j];
            float e = elp[(size_t)s*HEADS + h] + erv;
            e = e > 0.f ? e : NEG_SLOPE * e;
            m = fmaxf(m, e);
        }
        float den = 0.f;
        for (int j = p0; j < p1; j++) {
            int s = g_list[j];
            float e = elp[(size_t)s*HEADS + h] + erv;
            e = e > 0.f ? e : NEG_SLOPE * e;
            den += __expf(e - m);
        }
        float inv = 1.f / den;
        const float* zr = z + (size_t)r*NN*C1;
        for (int j = p0; j < p1; j++) {
            int s = g_list[j];
            float e = elp[(size_t)s*HEADS + h] + erv;
            e = e > 0.f ? e : NEG_SLOPE * e;
            float w = __expf(e - m) * inv;
            acc += w * zr[(size_t)s*C1 + c];
        }
    }
    float v = acc + b1[c] + b1[C1 + c] + b1[2*C1 + c];
    g_h[(size_t)n*C1 + c] = v > 0.f ? v : 0.f;
}

// ==================== fused GAT aggregation, layer 2 (+head mean) ====================
// one block (256 thr) per dst node; thread c owns channel c; h = c/64
__global__ __launch_bounds__(C2)
void gat_agg2(const float* __restrict__ z, const float* __restrict__ b2,
              float* __restrict__ out) {
    __shared__ float sred[C2];
    int n = blockIdx.x;
    int c = threadIdx.x, h = c >> 6;
    float acc = 0.f;
    #pragma unroll
    for (int r = 0; r < RR; r++) {
        int p0 = g_ptr[r*NN + n], p1 = g_ptr[r*NN + n + 1];
        if (p0 == p1) continue;
        float erv = g_er[((size_t)r*NN + n)*HEADS + h];
        const float* elp = g_el + (size_t)r*NN*HEADS;
        float m = -INFINITY;
        for (int j = p0; j < p1; j++) {
            int s = g_list[j];
            float e = elp[(size_t)s*HEADS + h] + erv;
            e = e > 0.f ? e : NEG_SLOPE * e;
            m = fmaxf(m, e);
        }
        float den = 0.f;
        for (int j = p0; j < p1; j++) {
            int s = g_list[j];
            float e = elp[(size_t)s*HEADS + h] + erv;
            e = e > 0.f ? e : NEG_SLOPE * e;
            den += __expf(e - m);
        }
        float inv = 1.f / den;
        const float* zr = z + (size_t)r*NN*C2;
        for (int j = p0; j < p1; j++) {
            int s = g_list[j];
            float e = elp[(size_t)s*HEADS + h] + erv;
            e = e > 0.f ? e : NEG_SLOPE * e;
            float w = __expf(e - m) * inv;
            acc += w * zr[(size_t)s*C2 + c];
        }
    }
    sred[c] = acc + b2[c] + b2[C2 + c] + b2[2*C2 + c];
    __syncthreads();
    if (c < OUTD)
        out[(size_t)n*OUTD + c] =
            0.25f * (sred[c] + sred[OUTD + c] + sred[2*OUTD + c] + sred[3*OUTD + c]);
}

// ==================== launch ====================
extern "C" void kernel_launch(void* const* d_in, const int* in_sizes, int n_in,
                              void* d_out, int out_size) {
    const float* x   = (const float*)d_in[0];
    const int*   src = (const int*)  d_in[1];
    const int*   dst = (const int*)  d_in[2];
    const float* W1  = (const float*)d_in[3];
    const float* al1 = (const float*)d_in[4];
    const float* ar1 = (const float*)d_in[5];
    const float* b1  = (const float*)d_in[6];
    const float* W2  = (const float*)d_in[7];
    const float* al2 = (const float*)d_in[8];
    const float* ar2 = (const float*)d_in[9];
    const float* b2  = (const float*)d_in[10];
    float* out = (float*)d_out;

    float *z1p, *z2p, *hp;
    cudaGetSymbolAddress((void**)&z1p, g_z1);
    cudaGetSymbolAddress((void**)&z2p, g_z2);
    cudaGetSymbolAddress((void**)&hp,  g_h);

    // ---- CSR build (shared by both layers) ----
    zero_cnt_k<<<(RR*NN + 255)/256, 256>>>();
    hist_k<<<(RR*EE + 255)/256, 256>>>(dst);
    scan_k<<<1, 1024>>>();
    fill_k<<<(RR*EE + 255)/256, 256>>>(src, dst);

    // ---- layer 1 ----
    sgemm_rel<<<dim3((NN+127)/128, C1/128, RR), 256>>>(x, W1, z1p, NN, C1, IND);
    attn_dots<<<RR*NN, 128>>>(z1p, al1, ar1, HID);
    gat_agg1<<<NN, C1>>>(z1p, b1);

    // ---- layer 2 ----
    sgemm_rel<<<dim3((NN+127)/128, C2/128, RR), 256>>>(hp, W2, z2p, NN, C2, C1);
    attn_dots<<<RR*NN, 128>>>(z2p, al2, ar2, OUTD);
    gat_agg2<<<NN, C2>>>(z2p, b2, out);
}

// round 3
// speedup vs baseline: 2.1942x; 1.4136x over previous
#include <cuda_runtime.h>
#include <math.h>
#include <stdint.h>

#define NN   30000
#define EE   300000
#define RR   3
#define IND  256
#define HID  32
#define OUTD 64
#define HEADS 4
#define C1 (HEADS*HID)    // 128
#define C2 (HEADS*OUTD)   // 256
#define NEG_SLOPE 0.2f

// -------------------- device scratch --------------------
__device__ float g_z1[(size_t)RR*NN*C1];
__device__ float g_z2[(size_t)RR*NN*C2];
__device__ float g_el[(size_t)RR*NN*HEADS];
__device__ float g_er[(size_t)RR*NN*HEADS];
__device__ float g_h [(size_t)NN*C1];
__device__ int g_cnt [(size_t)RR*NN];
__device__ int g_ptr [(size_t)RR*NN + 1];
__device__ int g_cur [(size_t)RR*NN];
__device__ int g_list[(size_t)RR*EE];

// ==================== CSR build ====================
__global__ void zero_cnt_k() {
    int i = blockIdx.x * blockDim.x + threadIdx.x;
    if (i < RR*NN) g_cnt[i] = 0;
}
__global__ void hist_k(const int* __restrict__ dst) {
    int i = blockIdx.x * blockDim.x + threadIdx.x;
    if (i >= RR*EE) return;
    int r = i / EE;
    atomicAdd(&g_cnt[r*NN + dst[i]], 1);
}
__global__ void scan_k() {
    __shared__ int s[1024];
    __shared__ int carry;
    int tid = threadIdx.x;
    if (tid == 0) carry = 0;
    __syncthreads();
    const int TOT = RR*NN;
    for (int base = 0; base < TOT; base += 1024) {
        int i = base + tid;
        int v = (i < TOT) ? g_cnt[i] : 0;
        s[tid] = v;
        __syncthreads();
        #pragma unroll
        for (int off = 1; off < 1024; off <<= 1) {
            int t = (tid >= off) ? s[tid - off] : 0;
            __syncthreads();
            s[tid] += t;
            __syncthreads();
        }
        if (i < TOT) {
            g_ptr[i] = carry + s[tid] - v;
            g_cur[i] = carry + s[tid] - v;
        }
        __syncthreads();
        if (tid == 1023) carry += s[1023];
        __syncthreads();
    }
    if (tid == 0) g_ptr[TOT] = carry;
}
__global__ void fill_k(const int* __restrict__ src, const int* __restrict__ dst) {
    int i = blockIdx.x * blockDim.x + threadIdx.x;
    if (i >= RR*EE) return;
    int r = i / EE;
    int pos = atomicAdd(&g_cur[r*NN + dst[i]], 1);
    g_list[pos] = src[i];
}

// ==================== TF32 tensor-core GEMM ====================
// C[r] = A @ B[r].  A:[M,K] shared, B:[R,K,N], C:[R,M,N].  K%32==0, N%128==0.
__device__ __forceinline__ uint32_t f2tf32(float f) {
    uint32_t u;
    asm("cvt.rna.tf32.f32 %0, %1;" : "=r"(u) : "f"(f));
    return u;
}

__global__ __launch_bounds__(256, 2)
void tf32gemm_rel(const float* __restrict__ A, const float* __restrict__ B,
                  float* __restrict__ C, int M, int N, int K) {
    const int BM = 128, BN = 128, BK = 32;
    int r = blockIdx.z;
    const float* Bp = B + (size_t)r * K * N;
    float*       Cp = C + (size_t)r * M * N;

    __shared__ float As[BM][BK + 4];   // bank = (4*row_grp + k) -> conflict-free frags
    __shared__ float Bs[BK][BN + 8];   // bank = (8*k_grp + n_grp) -> conflict-free frags

    int tid  = threadIdx.x;
    int lane = tid & 31;
    int wid  = tid >> 5;
    int warpRow = wid >> 2;     // 0..1  (64 rows each)
    int warpCol = wid & 3;      // 0..3  (32 cols each)
    int row0 = blockIdx.x * BM, col0 = blockIdx.y * BN;

    int lg = lane >> 2;         // 0..7
    int lt = lane & 3;          // 0..3

    float acc[4][4][4];
    #pragma unroll
    for (int i = 0; i < 4; i++)
        #pragma unroll
        for (int j = 0; j < 4; j++)
            #pragma unroll
            for (int q = 0; q < 4; q++) acc[i][j][q] = 0.f;

    // load mappings
    int aM = tid >> 3;          // 0..31 (plus 32*i)
    int aK4 = (tid & 7) * 4;
    int bK = tid >> 5;          // 0..7 (plus 8*i)
    int bN4 = (tid & 31) * 4;

    for (int k0 = 0; k0 < K; k0 += BK) {
        #pragma unroll
        for (int i = 0; i < 4; i++) {
            int m = aM + 32*i;
            int gm = row0 + m;
            float4 av = make_float4(0.f,0.f,0.f,0.f);
            if (gm < M) av = *(const float4*)&A[(size_t)gm*K + k0 + aK4];
            *(float4*)&As[m][aK4] = av;
        }
        #pragma unroll
        for (int i = 0; i < 4; i++) {
            int k = bK + 8*i;
            float4 bv = *(const float4*)&Bp[(size_t)(k0+k)*N + col0 + bN4];
            *(float4*)&Bs[k][bN4] = bv;
        }
        __syncthreads();

        #pragma unroll
        for (int kk = 0; kk < BK; kk += 8) {
            int c0 = kk + lt;
            uint32_t au[4][4], bu[4][2];
            #pragma unroll
            for (int mi = 0; mi < 4; mi++) {
                int rr = warpRow*64 + mi*16 + lg;
                au[mi][0] = f2tf32(As[rr  ][c0  ]);
                au[mi][1] = f2tf32(As[rr+8][c0  ]);
                au[mi][2] = f2tf32(As[rr  ][c0+4]);
                au[mi][3] = f2tf32(As[rr+8][c0+4]);
            }
            #pragma unroll
            for (int ni = 0; ni < 4; ni++) {
                int n = warpCol*32 + ni*8 + lg;
                bu[ni][0] = f2tf32(Bs[c0  ][n]);
                bu[ni][1] = f2tf32(Bs[c0+4][n]);
            }
            #pragma unroll
            for (int mi = 0; mi < 4; mi++)
                #pragma unroll
                for (int ni = 0; ni < 4; ni++) {
                    asm volatile(
                        "mma.sync.aligned.m16n8k8.row.col.f32.tf32.tf32.f32 "
                        "{%0,%1,%2,%3}, {%4,%5,%6,%7}, {%8,%9}, {%0,%1,%2,%3};"
                        : "+f"(acc[mi][ni][0]), "+f"(acc[mi][ni][1]),
                          "+f"(acc[mi][ni][2]), "+f"(acc[mi][ni][3])
                        : "r"(au[mi][0]), "r"(au[mi][1]), "r"(au[mi][2]), "r"(au[mi][3]),
                          "r"(bu[ni][0]), "r"(bu[ni][1]));
                }
        }
        __syncthreads();
    }

    // epilogue
    #pragma unroll
    for (int mi = 0; mi < 4; mi++) {
        int rA = row0 + warpRow*64 + mi*16 + lg;
        int rB = rA + 8;
        #pragma unroll
        for (int ni = 0; ni < 4; ni++) {
            int cc = col0 + warpCol*32 + ni*8 + 2*lt;
            if (rA < M) {
                float2 v = make_float2(acc[mi][ni][0], acc[mi][ni][1]);
                *(float2*)&Cp[(size_t)rA*N + cc] = v;
            }
            if (rB < M) {
                float2 v = make_float2(acc[mi][ni][2], acc[mi][ni][3]);
                *(float2*)&Cp[(size_t)rB*N + cc] = v;
            }
        }
    }
}

// ==================== attention dot products ====================
__global__ void attn_dots(const float* __restrict__ z, const float* __restrict__ al,
                          const float* __restrict__ ar, int D) {
    long bid = blockIdx.x;                   // r*NN + n
    int r = (int)(bid / NN);
    int t = threadIdx.x, h = t >> 5, lane = t & 31;
    int Ccols = HEADS * D;
    const float* zrow = z  + (size_t)bid * Ccols + h * D;
    const float* alp  = al + ((size_t)r*HEADS + h) * D;
    const float* arp  = ar + ((size_t)r*HEADS + h) * D;
    float vl = 0.f, vr = 0.f;
    for (int d = lane; d < D; d += 32) {
        float zv = zrow[d];
        vl += zv * alp[d];
        vr += zv * arp[d];
    }
    #pragma unroll
    for (int off = 16; off; off >>= 1) {
        vl += __shfl_down_sync(0xffffffffu, vl, off);
        vr += __shfl_down_sync(0xffffffffu, vr, off);
    }
    if (lane == 0) {
        g_el[(size_t)bid*HEADS + h] = vl;
        g_er[(size_t)bid*HEADS + h] = vr;
    }
}

// ==================== fused GAT aggregation (2-pass + prefetch) ====================
template<int C, int D>
__device__ __forceinline__ float gat_node(const float* __restrict__ z, int n, int c, int h) {
    float acc = 0.f;
    #pragma unroll
    for (int r = 0; r < RR; r++) {
        int p0 = g_ptr[r*NN + n], p1 = g_ptr[r*NN + n + 1];
        if (p0 == p1) continue;
        float erv = g_er[((size_t)r*NN + n)*HEADS + h];
        const float* elp = g_el + (size_t)r*NN*HEADS;
        // pass 1: max
        float m = -INFINITY;
        for (int j = p0; j < p1; j++) {
            int s = g_list[j];
            float e = elp[(size_t)s*HEADS + h] + erv;
            e = e > 0.f ? e : NEG_SLOPE * e;
            m = fmaxf(m, e);
        }
        // pass 2: den + unnormalized weighted sum, with prefetch
        const float* zr = z + (size_t)r*NN*C;
        float den = 0.f, loc = 0.f;
        int s = g_list[p0];
        float elv = elp[(size_t)s*HEADS + h];
        float zv  = zr[(size_t)s*C + c];
        for (int j = p0; j < p1; j++) {
            int jn = j + 1;
            int sn = 0; float eln = 0.f, zvn = 0.f;
            if (jn < p1) {
                sn = g_list[jn];
                eln = elp[(size_t)sn*HEADS + h];
                zvn = zr[(size_t)sn*C + c];
            }
            float e = elv + erv;
            e = e > 0.f ? e : NEG_SLOPE * e;
            float w = __expf(e - m);
            den += w;
            loc += w * zv;
            elv = eln; zv = zvn;
        }
        acc += loc * (1.f / den);
    }
    return acc;
}

__global__ __launch_bounds__(C1)
void gat_agg1(const float* __restrict__ z, const float* __restrict__ b1) {
    int n = blockIdx.x;
    int c = threadIdx.x, h = c >> 5;
    float acc = gat_node<C1, HID>(z, n, c, h);
    float v = acc + b1[c] + b1[C1 + c] + b1[2*C1 + c];
    g_h[(size_t)n*C1 + c] = v > 0.f ? v : 0.f;
}

__global__ __launch_bounds__(C2)
void gat_agg2(const float* __restrict__ z, const float* __restrict__ b2,
              float* __restrict__ out) {
    __shared__ float sred[C2];
    int n = blockIdx.x;
    int c = threadIdx.x, h = c >> 6;
    float acc = gat_node<C2, OUTD>(z, n, c, h);
    sred[c] = acc + b2[c] + b2[C2 + c] + b2[2*C2 + c];
    __syncthreads();
    if (c < OUTD)
        out[(size_t)n*OUTD + c] =
            0.25f * (sred[c] + sred[OUTD + c] + sred[2*OUTD + c] + sred[3*OUTD + c]);
}

// ==================== launch ====================
extern "C" void kernel_launch(void* const* d_in, const int* in_sizes, int n_in,
                              void* d_out, int out_size) {
    const float* x   = (const float*)d_in[0];
    const int*   src = (const int*)  d_in[1];
    const int*   dst = (const int*)  d_in[2];
    const float* W1  = (const float*)d_in[3];
    const float* al1 = (const float*)d_in[4];
    const float* ar1 = (const float*)d_in[5];
    const float* b1  = (const float*)d_in[6];
    const float* W2  = (const float*)d_in[7];
    const float* al2 = (const float*)d_in[8];
    const float* ar2 = (const float*)d_in[9];
    const float* b2  = (const float*)d_in[10];
    float* out = (float*)d_out;

    float *z1p, *z2p, *hp;
    cudaGetSymbolAddress((void**)&z1p, g_z1);
    cudaGetSymbolAddress((void**)&z2p, g_z2);
    cudaGetSymbolAddress((void**)&hp,  g_h);

    // ---- CSR build ----
    zero_cnt_k<<<(RR*NN + 255)/256, 256>>>();
    hist_k<<<(RR*EE + 255)/256, 256>>>(dst);
    scan_k<<<1, 1024>>>();
    fill_k<<<(RR*EE + 255)/256, 256>>>(src, dst);

    // ---- layer 1 ----
    tf32gemm_rel<<<dim3((NN+127)/128, C1/128, RR), 256>>>(x, W1, z1p, NN, C1, IND);
    attn_dots<<<RR*NN, 128>>>(z1p, al1, ar1, HID);
    gat_agg1<<<NN, C1>>>(z1p, b1);

    // ---- layer 2 ----
    tf32gemm_rel<<<dim3((NN+127)/128, C2/128, RR), 256>>>(hp, W2, z2p, NN, C2, C1);
    attn_dots<<<RR*NN, 128>>>(z2p, al2, ar2, OUTD);
    gat_agg2<<<NN, C2>>>(z2p, b2, out);
}

// round 4
// speedup vs baseline: 2.4501x; 1.1166x over previous
#include <cuda_runtime.h>
#include <math.h>
#include <stdint.h>

#define NN   30000
#define EE   300000
#define RR   3
#define IND  256
#define HID  32
#define OUTD 64
#define HEADS 4
#define C1 (HEADS*HID)    // 128
#define C2 (HEADS*OUTD)   // 256
#define NEG_SLOPE 0.2f

// -------------------- device scratch --------------------
__device__ float g_z1[(size_t)RR*NN*C1];
__device__ float g_z2[(size_t)RR*NN*C2];
__device__ float g_el[(size_t)RR*NN*HEADS];
__device__ float g_er[(size_t)RR*NN*HEADS];
__device__ float g_h [(size_t)NN*C1];
__device__ int g_cnt [(size_t)RR*NN];
__device__ int g_ptr [(size_t)RR*NN + 1];
__device__ int g_cur [(size_t)RR*NN];
__device__ int g_list[(size_t)RR*EE];

#define SCAN_TOT (RR*NN)          // 90000
#define SCAN_TPB 1024
#define SCAN_NBLK ((SCAN_TOT + SCAN_TPB - 1)/SCAN_TPB)   // 88
__device__ int g_blksum[SCAN_NBLK];

// ==================== CSR build ====================
__global__ void zero_cnt_k() {
    int i = blockIdx.x * blockDim.x + threadIdx.x;
    if (i < RR*NN) g_cnt[i] = 0;
}
__global__ void hist_k(const int* __restrict__ dst) {
    int i = blockIdx.x * blockDim.x + threadIdx.x;
    if (i >= RR*EE) return;
    int r = i / EE;
    atomicAdd(&g_cnt[r*NN + dst[i]], 1);
}
// per-block exclusive scan of one 1024 tile
__global__ void scan1_k() {
    __shared__ int s[SCAN_TPB];
    int tid = threadIdx.x;
    int i = blockIdx.x * SCAN_TPB + tid;
    int v = (i < SCAN_TOT) ? g_cnt[i] : 0;
    s[tid] = v;
    __syncthreads();
    #pragma unroll
    for (int off = 1; off < SCAN_TPB; off <<= 1) {
        int t = (tid >= off) ? s[tid - off] : 0;
        __syncthreads();
        s[tid] += t;
        __syncthreads();
    }
    if (i < SCAN_TOT) g_ptr[i] = s[tid] - v;     // tile-local exclusive
    if (tid == SCAN_TPB - 1) g_blksum[blockIdx.x] = s[tid];
}
// scan the 88 block sums (single small block)
__global__ void scan2_k() {
    __shared__ int s[128];
    int tid = threadIdx.x;
    int v = (tid < SCAN_NBLK) ? g_blksum[tid] : 0;
    s[tid] = v;
    __syncthreads();
    #pragma unroll
    for (int off = 1; off < 128; off <<= 1) {
        int t = (tid >= off) ? s[tid - off] : 0;
        __syncthreads();
        s[tid] += t;
        __syncthreads();
    }
    if (tid < SCAN_NBLK) g_blksum[tid] = s[tid] - v;   // exclusive
}
__global__ void scan3_k() {
    int i = blockIdx.x * blockDim.x + threadIdx.x;
    if (i < SCAN_TOT) {
        int p = g_ptr[i] + g_blksum[i / SCAN_TPB];
        g_ptr[i] = p;
        g_cur[i] = p;
    }
    if (i == 0) g_ptr[SCAN_TOT] = RR*EE;
}
__global__ void fill_k(const int* __restrict__ src, const int* __restrict__ dst) {
    int i = blockIdx.x * blockDim.x + threadIdx.x;
    if (i >= RR*EE) return;
    int r = i / EE;
    int pos = atomicAdd(&g_cur[r*NN + dst[i]], 1);
    g_list[pos] = src[i];
}

// ==================== TF32 tensor-core GEMM + fused attn dots ====================
__device__ __forceinline__ uint32_t f2tf32(float f) {
    uint32_t u;
    asm("cvt.rna.tf32.f32 %0, %1;" : "=r"(u) : "f"(f));
    return u;
}
__device__ __forceinline__ void cp_async16(uint32_t dst, const void* src, bool pred) {
    int sz = pred ? 16 : 0;
    asm volatile("cp.async.ca.shared.global [%0], [%1], 16, %2;\n"
                 :: "r"(dst), "l"(src), "r"(sz));
}
__device__ __forceinline__ void cp_commit() {
    asm volatile("cp.async.commit_group;\n");
}
template<int NWAIT>
__device__ __forceinline__ void cp_wait() {
    asm volatile("cp.async.wait_group %0;\n" :: "n"(NWAIT));
}

#define GEMM_SMEM_BYTES ((2*128*36 + 2*32*136) * 4)   // 71680

// C[r] = A @ B[r]; also computes el/er (attention dots) from the accumulators.
// D = head dim. Each warp's 32 columns lie inside exactly one head.
template<int D>
__global__ __launch_bounds__(256, 2)
void tf32gemm_attn(const float* __restrict__ A, const float* __restrict__ B,
                   float* __restrict__ C, const float* __restrict__ AL,
                   const float* __restrict__ AR, float* __restrict__ EL,
                   float* __restrict__ ER, int M, int N, int K) {
    const int BM = 128, BN = 128, BK = 32;
    extern __shared__ float smem[];
    float* As = smem;                  // [2][128][36]
    float* Bs = smem + 2*128*36;       // [2][32][136]

    int r = blockIdx.z;
    const float* Bp = B + (size_t)r * K * N;
    float*       Cp = C + (size_t)r * M * N;
    const float* alp = AL + (size_t)r * N;   // flat [HEADS*D] == [N]
    const float* arp = AR + (size_t)r * N;

    int tid  = threadIdx.x;
    int lane = tid & 31;
    int wid  = tid >> 5;
    int warpRow = wid >> 2;
    int warpCol = wid & 3;
    int row0 = blockIdx.x * BM, col0 = blockIdx.y * BN;
    int lg = lane >> 2;
    int lt = lane & 3;

    float acc[4][4][4];
    #pragma unroll
    for (int i = 0; i < 4; i++)
        #pragma unroll
        for (int j = 0; j < 4; j++)
            #pragma unroll
            for (int q = 0; q < 4; q++) acc[i][j][q] = 0.f;

    uint32_t asBase = (uint32_t)__cvta_generic_to_shared(As);
    uint32_t bsBase = (uint32_t)__cvta_generic_to_shared(Bs);
    int aM = tid >> 3;          // +32*i
    int aK4 = (tid & 7) * 4;
    int bK = tid >> 5;          // +8*i
    int bN4 = (tid & 31) * 4;

    const int KT = K / BK;

    // prologue: stage 0
    {
        #pragma unroll
        for (int i = 0; i < 4; i++) {
            int m = aM + 32*i, gm = row0 + m;
            int gmc = gm < M ? gm : M - 1;
            cp_async16(asBase + (uint32_t)((0*128 + m)*36 + aK4)*4,
                       &A[(size_t)gmc*K + aK4], gm < M);
        }
        #pragma unroll
        for (int i = 0; i < 4; i++) {
            int k = bK + 8*i;
            cp_async16(bsBase + (uint32_t)((0*32 + k)*136 + bN4)*4,
                       &Bp[(size_t)k*N + col0 + bN4], true);
        }
        cp_commit();
    }

    for (int kt = 0; kt < KT; kt++) {
        int cur = kt & 1;
        if (kt + 1 < KT) {
            int nst = cur ^ 1;
            int k0 = (kt + 1) * BK;
            #pragma unroll
            for (int i = 0; i < 4; i++) {
                int m = aM + 32*i, gm = row0 + m;
                int gmc = gm < M ? gm : M - 1;
                cp_async16(asBase + (uint32_t)((nst*128 + m)*36 + aK4)*4,
                           &A[(size_t)gmc*K + k0 + aK4], gm < M);
            }
            #pragma unroll
            for (int i = 0; i < 4; i++) {
                int k = bK + 8*i;
                cp_async16(bsBase + (uint32_t)((nst*32 + k)*136 + bN4)*4,
                           &Bp[(size_t)(k0+k)*N + col0 + bN4], true);
            }
            cp_commit();
            cp_wait<1>();
        } else {
            cp_wait<0>();
        }
        __syncthreads();

        const float* Asl = As + (size_t)cur*128*36;
        const float* Bsl = Bs + (size_t)cur*32*136;
        #pragma unroll
        for (int kk = 0; kk < BK; kk += 8) {
            int c0 = kk + lt;
            uint32_t au[4][4], bu[4][2];
            #pragma unroll
            for (int mi = 0; mi < 4; mi++) {
                int rr = warpRow*64 + mi*16 + lg;
                au[mi][0] = f2tf32(Asl[(rr  )*36 + c0  ]);
                au[mi][1] = f2tf32(Asl[(rr+8)*36 + c0  ]);
                au[mi][2] = f2tf32(Asl[(rr  )*36 + c0+4]);
                au[mi][3] = f2tf32(Asl[(rr+8)*36 + c0+4]);
            }
            #pragma unroll
            for (int ni = 0; ni < 4; ni++) {
                int n = warpCol*32 + ni*8 + lg;
                bu[ni][0] = f2tf32(Bsl[(c0  )*136 + n]);
                bu[ni][1] = f2tf32(Bsl[(c0+4)*136 + n]);
            }
            #pragma unroll
            for (int mi = 0; mi < 4; mi++)
                #pragma unroll
                for (int ni = 0; ni < 4; ni++) {
                    asm volatile(
                        "mma.sync.aligned.m16n8k8.row.col.f32.tf32.tf32.f32 "
                        "{%0,%1,%2,%3}, {%4,%5,%6,%7}, {%8,%9}, {%0,%1,%2,%3};"
                        : "+f"(acc[mi][ni][0]), "+f"(acc[mi][ni][1]),
                          "+f"(acc[mi][ni][2]), "+f"(acc[mi][ni][3])
                        : "r"(au[mi][0]), "r"(au[mi][1]), "r"(au[mi][2]), "r"(au[mi][3]),
                          "r"(bu[ni][0]), "r"(bu[ni][1]));
                }
        }
        __syncthreads();
    }

    // ---- epilogue 1: store C ----
    #pragma unroll
    for (int mi = 0; mi < 4; mi++) {
        int rA = row0 + warpRow*64 + mi*16 + lg;
        int rB = rA + 8;
        #pragma unroll
        for (int ni = 0; ni < 4; ni++) {
            int cc = col0 + warpCol*32 + ni*8 + 2*lt;
            if (rA < M) *(float2*)&Cp[(size_t)rA*N + cc] =
                make_float2(acc[mi][ni][0], acc[mi][ni][1]);
            if (rB < M) *(float2*)&Cp[(size_t)rB*N + cc] =
                make_float2(acc[mi][ni][2], acc[mi][ni][3]);
        }
    }

    // ---- epilogue 2: fused attention dots ----
    const int HBLK = BN / D;                 // heads covered by this block
    int headLocal = (warpCol*32) / D;        // this warp's head (block-local)
    int headBase  = col0 / D;

    float* sEl = smem;                       // reuse As region: [HBLK][128]
    float* sEr = smem + HBLK*BM;
    for (int i = tid; i < 2*HBLK*BM; i += 256) smem[i] = 0.f;
    __syncthreads();

    float alv[8], arv[8];
    #pragma unroll
    for (int ni = 0; ni < 4; ni++)
        #pragma unroll
        for (int q = 0; q < 2; q++) {
            int cl = warpCol*32 + ni*8 + 2*lt + q;
            alv[ni*2+q] = alp[col0 + cl];
            arv[ni*2+q] = arp[col0 + cl];
        }

    #pragma unroll
    for (int mi = 0; mi < 4; mi++) {
        float elA = 0.f, erA = 0.f, elB = 0.f, erB = 0.f;
        #pragma unroll
        for (int ni = 0; ni < 4; ni++)
            #pragma unroll
            for (int q = 0; q < 2; q++) {
                elA += acc[mi][ni][q]   * alv[ni*2+q];
                erA += acc[mi][ni][q]   * arv[ni*2+q];
                elB += acc[mi][ni][2+q] * alv[ni*2+q];
                erB += acc[mi][ni][2+q] * arv[ni*2+q];
            }
        #pragma unroll
        for (int off = 1; off <= 2; off <<= 1) {
            elA += __shfl_xor_sync(0xffffffffu, elA, off);
            erA += __shfl_xor_sync(0xffffffffu, erA, off);
            elB += __shfl_xor_sync(0xffffffffu, elB, off);
            erB += __shfl_xor_sync(0xffffffffu, erB, off);
        }
        if (lt == 0) {
            int ra = warpRow*64 + mi*16 + lg;
            atomicAdd(&sEl[headLocal*BM + ra],     elA);
            atomicAdd(&sEr[headLocal*BM + ra],     erA);
            atomicAdd(&sEl[headLocal*BM + ra + 8], elB);
            atomicAdd(&sEr[headLocal*BM + ra + 8], erB);
        }
    }
    __syncthreads();

    for (int i = tid; i < HBLK*BM; i += 256) {
        int hh = i >> 7, row = i & 127;
        int gm = row0 + row;
        if (gm < M) {
            size_t o = ((size_t)r*NN + gm)*HEADS + headBase + hh;
            EL[o] = sEl[hh*BM + row];
            ER[o] = sEr[hh*BM + row];
        }
    }
}

// ==================== fused GAT aggregation (chunked prefetch) ====================
template<int C>
__device__ __forceinline__ float gat_node(const float* __restrict__ z, int n, int c, int h) {
    float acc = 0.f;
    #pragma unroll
    for (int r = 0; r < RR; r++) {
        int p0 = g_ptr[r*NN + n], p1 = g_ptr[r*NN + n + 1];
        if (p0 == p1) continue;
        float erv = g_er[((size_t)r*NN + n)*HEADS + h];
        const float* elp = g_el + (size_t)r*NN*HEADS;
        // pass 1: max (chunked, MLP=8)
        float m = -INFINITY;
        for (int jb = p0; jb < p1; jb += 8) {
            float ev[8];
            #pragma unroll
            for (int t = 0; t < 8; t++) {
                int j = jb + t;
                ev[t] = (j < p1) ? elp[(size_t)g_list[j]*HEADS + h] : -INFINITY;
            }
            #pragma unroll
            for (int t = 0; t < 8; t++) {
                float e = ev[t] + erv;
                e = e > 0.f ? e : NEG_SLOPE * e;
                m = fmaxf(m, e);
            }
        }
        // pass 2: den + weighted sum (chunked, MLP=4)
        const float* zr = z + (size_t)r*NN*C;
        float den = 0.f, loc = 0.f;
        for (int jb = p0; jb < p1; jb += 4) {
            int ss[4]; float ev[4], zv[4];
            #pragma unroll
            for (int t = 0; t < 4; t++) {
                int j = jb + t;
                ss[t] = (j < p1) ? g_list[j] : 0;
            }
            #pragma unroll
            for (int t = 0; t < 4; t++) {
                ev[t] = elp[(size_t)ss[t]*HEADS + h];
                zv[t] = zr[(size_t)ss[t]*C + c];
            }
            #pragma unroll
            for (int t = 0; t < 4; t++) {
                if (jb + t < p1) {
                    float e = ev[t] + erv;
                    e = e > 0.f ? e : NEG_SLOPE * e;
                    float w = __expf(e - m);
                    den += w;
                    loc += w * zv[t];
                }
            }
        }
        acc += loc * (1.f / den);
    }
    return acc;
}

__global__ __launch_bounds__(C1)
void gat_agg1(const float* __restrict__ z, const float* __restrict__ b1) {
    int n = blockIdx.x;
    int c = threadIdx.x, h = c >> 5;
    float acc = gat_node<C1>(z, n, c, h);
    float v = acc + b1[c] + b1[C1 + c] + b1[2*C1 + c];
    g_h[(size_t)n*C1 + c] = v > 0.f ? v : 0.f;
}

__global__ __launch_bounds__(C2)
void gat_agg2(const float* __restrict__ z, const float* __restrict__ b2,
              float* __restrict__ out) {
    __shared__ float sred[C2];
    int n = blockIdx.x;
    int c = threadIdx.x, h = c >> 6;
    float acc = gat_node<C2>(z, n, c, h);
    sred[c] = acc + b2[c] + b2[C2 + c] + b2[2*C2 + c];
    __syncthreads();
    if (c < OUTD)
        out[(size_t)n*OUTD + c] =
            0.25f * (sred[c] + sred[OUTD + c] + sred[2*OUTD + c] + sred[3*OUTD + c]);
}

// ==================== launch ====================
extern "C" void kernel_launch(void* const* d_in, const int* in_sizes, int n_in,
                              void* d_out, int out_size) {
    const float* x   = (const float*)d_in[0];
    const int*   src = (const int*)  d_in[1];
    const int*   dst = (const int*)  d_in[2];
    const float* W1  = (const float*)d_in[3];
    const float* al1 = (const float*)d_in[4];
    const float* ar1 = (const float*)d_in[5];
    const float* b1  = (const float*)d_in[6];
    const float* W2  = (const float*)d_in[7];
    const float* al2 = (const float*)d_in[8];
    const float* ar2 = (const float*)d_in[9];
    const float* b2  = (const float*)d_in[10];
    float* out = (float*)d_out;

    float *z1p, *z2p, *hp, *elp, *erp;
    cudaGetSymbolAddress((void**)&z1p, g_z1);
    cudaGetSymbolAddress((void**)&z2p, g_z2);
    cudaGetSymbolAddress((void**)&hp,  g_h);
    cudaGetSymbolAddress((void**)&elp, g_el);
    cudaGetSymbolAddress((void**)&erp, g_er);

    static bool attr_done = false;
    if (!attr_done) {
        cudaFuncSetAttribute(tf32gemm_attn<HID>,
                             cudaFuncAttributeMaxDynamicSharedMemorySize, GEMM_SMEM_BYTES);
        cudaFuncSetAttribute(tf32gemm_attn<OUTD>,
                             cudaFuncAttributeMaxDynamicSharedMemorySize, GEMM_SMEM_BYTES);
        attr_done = true;
    }

    // ---- CSR build ----
    zero_cnt_k<<<(RR*NN + 255)/256, 256>>>();
    hist_k<<<(RR*EE + 255)/256, 256>>>(dst);
    scan1_k<<<SCAN_NBLK, SCAN_TPB>>>();
    scan2_k<<<1, 128>>>();
    scan3_k<<<(SCAN_TOT + 255)/256, 256>>>();
    fill_k<<<(RR*EE + 255)/256, 256>>>(src, dst);

    // ---- layer 1 ----
    tf32gemm_attn<HID><<<dim3((NN+127)/128, C1/128, RR), 256, GEMM_SMEM_BYTES>>>(
        x, W1, z1p, al1, ar1, elp, erp, NN, C1, IND);
    gat_agg1<<<NN, C1>>>(z1p, b1);

    // ---- layer 2 ----
    tf32gemm_attn<OUTD><<<dim3((NN+127)/128, C2/128, RR), 256, GEMM_SMEM_BYTES>>>(
        hp, W2, z2p, al2, ar2, elp, erp, NN, C2, C1);
    gat_agg2<<<NN, C2>>>(z2p, b2, out);
}